// round 12
// baseline (speedup 1.0000x reference)
#include <cuda_runtime.h>
#include <cuda_bf16.h>
#include <math.h>

// PLIF neuron scan: x[B,T,C] -> spikes[B,T,C]
//   v = v*sigmoid(decay_param[c]) + x[b,t,c]; s = (v > 0.5); v -= 0.5*s
// B=128, T=256, C=2048.
//
// FINAL (R12 = R10/R11, twice confirmed at bench 88.128us):
//  - one block per batch row: grid=128, block=512, thread = 4 channels
//    (float4); read & write streams each sequential 2MB per block.
//  - PF=8 register prefetch ring (A/B proven: 8 > 16, 8 > burst-8).
//  - __ldcs streaming loads, __stwt write-through stores.
// Plateau evidence (R1-R11): MLP depth, occupancy, block geometry,
// stream layout, R/W batching, and store cache-op all converge at
// DRAM 76-79% / 6.0-6.25 TB/s -> achievable mixed R/W HBM ceiling for
// this irreducible 512MB stream. Split-T parallelization rejected
// (adds traffic on a BW-bound kernel); TMA path rejected (LTS-cap is
// path-independent per B300 microarch).

#define T_STEPS 256
#define C_CH    2048
#define GROUPS  (C_CH / 4)   // 512 float4 groups = one full row per block
#define PF      8            // prefetch depth

static_assert((T_STEPS - PF) % PF == 0, "steady loop must be multiple of PF");

__global__ __launch_bounds__(512, 1)   // 128-reg cap; body 78 regs, no spill
void plif_scan_kernel(const float* __restrict__ x,
                      const float* __restrict__ decay_param,
                      float* __restrict__ out)
{
    const int g = threadIdx.x;           // float4 group within C (0..511)
    const int b = blockIdx.x;            // batch row (0..127)

    // Per-channel decay = sigmoid(decay_param). Computed once; IEEE expf to
    // avoid compounded drift over 256 recurrence steps.
    const float4 dp = reinterpret_cast<const float4*>(decay_param)[g];
    const float d0 = 1.0f / (1.0f + expf(-dp.x));
    const float d1 = 1.0f / (1.0f + expf(-dp.y));
    const float d2 = 1.0f / (1.0f + expf(-dp.z));
    const float d3 = 1.0f / (1.0f + expf(-dp.w));

    const float4* xp = reinterpret_cast<const float4*>(x)
                     + (size_t)b * (T_STEPS * GROUPS) + g;
    float4*       op = reinterpret_cast<float4*>(out)
                     + (size_t)b * (T_STEPS * GROUPS) + g;

    float v0 = 0.0f, v1 = 0.0f, v2 = 0.0f, v3 = 0.0f;

    // Prime the ring: PF independent in-flight LDG.128 per thread.
    float4 buf[PF];
#pragma unroll
    for (int i = 0; i < PF; i++)
        buf[i] = __ldcs(xp + i * GROUPS);

#define PLIF_STEP(CUR)                                                  \
    do {                                                                \
        v0 = fmaf(v0, d0, (CUR).x);                                     \
        v1 = fmaf(v1, d1, (CUR).y);                                     \
        v2 = fmaf(v2, d2, (CUR).z);                                     \
        v3 = fmaf(v3, d3, (CUR).w);                                     \
        const float s0 = (v0 > 0.5f) ? 1.0f : 0.0f;                     \
        const float s1 = (v1 > 0.5f) ? 1.0f : 0.0f;                     \
        const float s2 = (v2 > 0.5f) ? 1.0f : 0.0f;                     \
        const float s3 = (v3 > 0.5f) ? 1.0f : 0.0f;                     \
        v0 = fmaf(s0, -0.5f, v0);                                       \
        v1 = fmaf(s1, -0.5f, v1);                                       \
        v2 = fmaf(s2, -0.5f, v2);                                       \
        v3 = fmaf(s3, -0.5f, v3);                                       \
        __stwt(op + t * GROUPS, make_float4(s0, s1, s2, s3));           \
    } while (0)

    // Steady state: 248 iters = 31 * 8; unroll-8 keeps the ring index a
    // compile-time constant (pure registers).
#pragma unroll 8
    for (int t = 0; t < T_STEPS - PF; t++) {
        const float4 cur = buf[t & (PF - 1)];
        buf[t & (PF - 1)] = __ldcs(xp + (t + PF) * GROUPS);
        PLIF_STEP(cur);
    }

    // Epilogue: drain the ring, no further loads.
#pragma unroll
    for (int t = T_STEPS - PF; t < T_STEPS; t++) {
        const float4 cur = buf[t & (PF - 1)];
        PLIF_STEP(cur);
    }
#undef PLIF_STEP
}

extern "C" void kernel_launch(void* const* d_in, const int* in_sizes, int n_in,
                              void* d_out, int out_size)
{
    const float* x  = (const float*)d_in[0];        // [128, 256, 2048]
    const float* dp = (const float*)d_in[1];        // [2048]
    float*       o  = (float*)d_out;                // [128, 256, 2048]

    plif_scan_kernel<<<128, 512>>>(x, dp, o);       // one block per batch row
}

// round 13
// speedup vs baseline: 1.0036x; 1.0036x over previous
#include <cuda_runtime.h>
#include <cuda_bf16.h>
#include <math.h>

// PLIF neuron scan: x[B,T,C] -> spikes[B,T,C]
//   v = v*sigmoid(decay_param[c]) + x[b,t,c]; s = (v > 0.5); v -= 0.5*s
// B=128, T=256, C=2048.
//
// FINAL (confirmed 3x at bench 88.128us; kernel 78-80us):
//  - one block per batch row: grid=128, block=512, thread = 4 channels
//    (float4); read & write streams each sequential 2MB per block.
//  - PF=8 register prefetch ring (A/B proven: 8 > 16, 8 > burst-8).
//  - __ldcs streaming loads, __stwt write-through stores.
//
// Plateau evidence (R1-R12): MLP depth (8/16), occupancy (20-40%),
// block geometry (128/256/512), sequential vs strided streams, R/W
// burst batching, and store cache-op (cs/wt) all converge at
// DRAM 76-79% / 6.0-6.25 TB/s, with +-2.5% run-to-run noise on the
// same binary. 512MB of irreducible traffic at that rate IS the
// kernel time. Rejected on theory: LDG.256 (sector stream unchanged,
// SASS width caps at .128), TMA-staged stores (LTS cap is
// path-independent; controller schedules R/W mix, not the kernel),
// split-T speculative scan (spike-flip correctness risk),
// traffic reduction (dtypes fixed by harness).

#define T_STEPS 256
#define C_CH    2048
#define GROUPS  (C_CH / 4)   // 512 float4 groups = one full row per block
#define PF      8            // prefetch depth

static_assert((T_STEPS - PF) % PF == 0, "steady loop must be multiple of PF");

__global__ __launch_bounds__(512, 1)   // 128-reg cap; body 78 regs, no spill
void plif_scan_kernel(const float* __restrict__ x,
                      const float* __restrict__ decay_param,
                      float* __restrict__ out)
{
    const int g = threadIdx.x;           // float4 group within C (0..511)
    const int b = blockIdx.x;            // batch row (0..127)

    // Per-channel decay = sigmoid(decay_param). Computed once; IEEE expf to
    // avoid compounded drift over 256 recurrence steps.
    const float4 dp = reinterpret_cast<const float4*>(decay_param)[g];
    const float d0 = 1.0f / (1.0f + expf(-dp.x));
    const float d1 = 1.0f / (1.0f + expf(-dp.y));
    const float d2 = 1.0f / (1.0f + expf(-dp.z));
    const float d3 = 1.0f / (1.0f + expf(-dp.w));

    const float4* xp = reinterpret_cast<const float4*>(x)
                     + (size_t)b * (T_STEPS * GROUPS) + g;
    float4*       op = reinterpret_cast<float4*>(out)
                     + (size_t)b * (T_STEPS * GROUPS) + g;

    float v0 = 0.0f, v1 = 0.0f, v2 = 0.0f, v3 = 0.0f;

    // Prime the ring: PF independent in-flight LDG.128 per thread.
    float4 buf[PF];
#pragma unroll
    for (int i = 0; i < PF; i++)
        buf[i] = __ldcs(xp + i * GROUPS);

#define PLIF_STEP(CUR)                                                  \
    do {                                                                \
        v0 = fmaf(v0, d0, (CUR).x);                                     \
        v1 = fmaf(v1, d1, (CUR).y);                                     \
        v2 = fmaf(v2, d2, (CUR).z);                                     \
        v3 = fmaf(v3, d3, (CUR).w);                                     \
        const float s0 = (v0 > 0.5f) ? 1.0f : 0.0f;                     \
        const float s1 = (v1 > 0.5f) ? 1.0f : 0.0f;                     \
        const float s2 = (v2 > 0.5f) ? 1.0f : 0.0f;                     \
        const float s3 = (v3 > 0.5f) ? 1.0f : 0.0f;                     \
        v0 = fmaf(s0, -0.5f, v0);                                       \
        v1 = fmaf(s1, -0.5f, v1);                                       \
        v2 = fmaf(s2, -0.5f, v2);                                       \
        v3 = fmaf(s3, -0.5f, v3);                                       \
        __stwt(op + t * GROUPS, make_float4(s0, s1, s2, s3));           \
    } while (0)

    // Steady state: 248 iters = 31 * 8; unroll-8 keeps the ring index a
    // compile-time constant (pure registers).
#pragma unroll 8
    for (int t = 0; t < T_STEPS - PF; t++) {
        const float4 cur = buf[t & (PF - 1)];
        buf[t & (PF - 1)] = __ldcs(xp + (t + PF) * GROUPS);
        PLIF_STEP(cur);
    }

    // Epilogue: drain the ring, no further loads.
#pragma unroll
    for (int t = T_STEPS - PF; t < T_STEPS; t++) {
        const float4 cur = buf[t & (PF - 1)];
        PLIF_STEP(cur);
    }
#undef PLIF_STEP
}

extern "C" void kernel_launch(void* const* d_in, const int* in_sizes, int n_in,
                              void* d_out, int out_size)
{
    const float* x  = (const float*)d_in[0];        // [128, 256, 2048]
    const float* dp = (const float*)d_in[1];        // [2048]
    float*       o  = (float*)d_out;                // [128, 256, 2048]

    plif_scan_kernel<<<128, 512>>>(x, dp, o);       // one block per batch row
}

// round 14
// speedup vs baseline: 1.0062x; 1.0026x over previous
#include <cuda_runtime.h>
#include <cuda_bf16.h>
#include <math.h>

// PLIF neuron scan: x[B,T,C] -> spikes[B,T,C]
//   v = v*sigmoid(decay_param[c]) + x[b,t,c]; s = (v > 0.5); v -= 0.5*s
// B=128, T=256, C=2048.
//
// FINAL (confirmed 4x: bench 87.8-88.1us; kernel 78-80us; DRAM 76-79%):
//  - one block per batch row: grid=128, block=512, thread = 4 channels
//    (float4); read & write streams each sequential 2MB per block.
//  - PF=8 register prefetch ring (A/B proven: 8 > 16, 8 > burst-8).
//  - __ldcs streaming loads, __stwt write-through stores.
//
// Plateau evidence (R1-R13): MLP depth (8/16), occupancy (20-40%),
// block geometry (128/256/512), sequential vs strided streams, R/W
// burst batching, and store cache-op (cs/wt) all converge at
// DRAM 76-79% / 6.0-6.25 TB/s, with +-2.5% run-to-run noise on the
// same binary. 512MB of irreducible traffic at that rate IS the
// kernel time. Rejected on theory: LDG.256 (sector stream unchanged,
// SASS width caps at .128), TMA-staged stores (LTS cap is
// path-independent; controller schedules R/W mix, not the kernel),
// split-T speculative scan (spike-flip correctness risk),
// traffic reduction (dtypes fixed by harness).

#define T_STEPS 256
#define C_CH    2048
#define GROUPS  (C_CH / 4)   // 512 float4 groups = one full row per block
#define PF      8            // prefetch depth

static_assert((T_STEPS - PF) % PF == 0, "steady loop must be multiple of PF");

__global__ __launch_bounds__(512, 1)   // 128-reg cap; body 78 regs, no spill
void plif_scan_kernel(const float* __restrict__ x,
                      const float* __restrict__ decay_param,
                      float* __restrict__ out)
{
    const int g = threadIdx.x;           // float4 group within C (0..511)
    const int b = blockIdx.x;            // batch row (0..127)

    // Per-channel decay = sigmoid(decay_param). Computed once; IEEE expf to
    // avoid compounded drift over 256 recurrence steps.
    const float4 dp = reinterpret_cast<const float4*>(decay_param)[g];
    const float d0 = 1.0f / (1.0f + expf(-dp.x));
    const float d1 = 1.0f / (1.0f + expf(-dp.y));
    const float d2 = 1.0f / (1.0f + expf(-dp.z));
    const float d3 = 1.0f / (1.0f + expf(-dp.w));

    const float4* xp = reinterpret_cast<const float4*>(x)
                     + (size_t)b * (T_STEPS * GROUPS) + g;
    float4*       op = reinterpret_cast<float4*>(out)
                     + (size_t)b * (T_STEPS * GROUPS) + g;

    float v0 = 0.0f, v1 = 0.0f, v2 = 0.0f, v3 = 0.0f;

    // Prime the ring: PF independent in-flight LDG.128 per thread.
    float4 buf[PF];
#pragma unroll
    for (int i = 0; i < PF; i++)
        buf[i] = __ldcs(xp + i * GROUPS);

#define PLIF_STEP(CUR)                                                  \
    do {                                                                \
        v0 = fmaf(v0, d0, (CUR).x);                                     \
        v1 = fmaf(v1, d1, (CUR).y);                                     \
        v2 = fmaf(v2, d2, (CUR).z);                                     \
        v3 = fmaf(v3, d3, (CUR).w);                                     \
        const float s0 = (v0 > 0.5f) ? 1.0f : 0.0f;                     \
        const float s1 = (v1 > 0.5f) ? 1.0f : 0.0f;                     \
        const float s2 = (v2 > 0.5f) ? 1.0f : 0.0f;                     \
        const float s3 = (v3 > 0.5f) ? 1.0f : 0.0f;                     \
        v0 = fmaf(s0, -0.5f, v0);                                       \
        v1 = fmaf(s1, -0.5f, v1);                                       \
        v2 = fmaf(s2, -0.5f, v2);                                       \
        v3 = fmaf(s3, -0.5f, v3);                                       \
        __stwt(op + t * GROUPS, make_float4(s0, s1, s2, s3));           \
    } while (0)

    // Steady state: 248 iters = 31 * 8; unroll-8 keeps the ring index a
    // compile-time constant (pure registers).
#pragma unroll 8
    for (int t = 0; t < T_STEPS - PF; t++) {
        const float4 cur = buf[t & (PF - 1)];
        buf[t & (PF - 1)] = __ldcs(xp + (t + PF) * GROUPS);
        PLIF_STEP(cur);
    }

    // Epilogue: drain the ring, no further loads.
#pragma unroll
    for (int t = T_STEPS - PF; t < T_STEPS; t++) {
        const float4 cur = buf[t & (PF - 1)];
        PLIF_STEP(cur);
    }
#undef PLIF_STEP
}

extern "C" void kernel_launch(void* const* d_in, const int* in_sizes, int n_in,
                              void* d_out, int out_size)
{
    const float* x  = (const float*)d_in[0];        // [128, 256, 2048]
    const float* dp = (const float*)d_in[1];        // [2048]
    float*       o  = (float*)d_out;                // [128, 256, 2048]

    plif_scan_kernel<<<128, 512>>>(x, dp, o);       // one block per batch row
}